// round 12
// baseline (speedup 1.0000x reference)
#include <cuda_runtime.h>
#include <cuda_bf16.h>

#define BATCH 32768
#define EMB   2048
#define FEAT  320
#define KACT  103          // ceil(0.05*2048)
#define MARGIN_MIN 2e-4f   // > 2*(|z_fast-z_exact| + |z_ref-z_exact|) bound (3-product split)

// ---- GEMM tiling ----
#define TM 128
#define TN 128
#define NCHUNK 5           // FEAT / 64
#define TILE_B 16384       // one split tile: 128 rows x 128B (swizzled)
#define STAGE_B 65536      // A0,A1,B0,B1
#define SMEM_GEMM (3*STAGE_B + 64)   // 196672; epilogue reuse 128*132*4=67584 fits

// ---- device scratch (no allocs allowed) ----
// pre-swizzled tiled splits: [split][(tile*NCHUNK + chunk)*16KB]
__device__ __align__(16) char g_Aw[2][(BATCH/128) * NCHUNK * TILE_B];  // 2 x 20 MB
__device__ __align__(16) char g_Bw[2][(EMB/128)   * NCHUNK * TILE_B];  // 2 x 1.25 MB
__device__ float    g_hf[BATCH * FEAT];        // exact fp32 h for fixup, 42 MB
__device__ unsigned g_z[(size_t)BATCH * EMB];  // order-preserving z keys, 268 MB
__device__ int      g_nrisky;
__device__ int      g_risky[BATCH];

// ================= helpers =================
__device__ __forceinline__ unsigned smem_u32(const void* p) {
    unsigned a;
    asm("{ .reg .u64 t; cvta.to.shared.u64 t, %1; cvt.u32.u64 %0, t; }" : "=r"(a) : "l"(p));
    return a;
}
__device__ __forceinline__ void mbar_init(unsigned a, unsigned cnt) {
    asm volatile("mbarrier.init.shared.b64 [%0], %1;" :: "r"(a), "r"(cnt) : "memory");
}
__device__ __forceinline__ void mbar_expect_tx(unsigned a, unsigned bytes) {
    asm volatile("mbarrier.arrive.expect_tx.shared.b64 _, [%0], %1;" :: "r"(a), "r"(bytes) : "memory");
}
__device__ __forceinline__ void mbar_wait(unsigned a, unsigned parity) {
    asm volatile("{\n\t.reg .pred P;\n\tWL_%=:\n\t"
                 "mbarrier.try_wait.parity.acquire.cta.shared::cta.b64 P, [%0], %1, 0x989680;\n\t"
                 "@P bra.uni WD_%=;\n\tbra.uni WL_%=;\n\tWD_%=:\n\t}"
                 :: "r"(a), "r"(parity) : "memory");
}
__device__ __forceinline__ void bulkcp(unsigned dsmem, const void* gsrc, unsigned bytes, unsigned mbar) {
    asm volatile("cp.async.bulk.shared::cluster.global.mbarrier::complete_tx::bytes "
                 "[%0], [%1], %2, [%3];"
                 :: "r"(dsmem), "l"(gsrc), "r"(bytes), "r"(mbar) : "memory");
}
__device__ __forceinline__ void ldsm4(unsigned& r0, unsigned& r1, unsigned& r2, unsigned& r3, unsigned a) {
    asm volatile("ldmatrix.sync.aligned.m8n8.x4.shared.b16 {%0,%1,%2,%3}, [%4];"
                 : "=r"(r0), "=r"(r1), "=r"(r2), "=r"(r3) : "r"(a));
}
__device__ __forceinline__ void ldsm2(unsigned& r0, unsigned& r1, unsigned a) {
    asm volatile("ldmatrix.sync.aligned.m8n8.x2.shared.b16 {%0,%1}, [%2];"
                 : "=r"(r0), "=r"(r1) : "r"(a));
}
__device__ __forceinline__ void mma16816(float* c, const unsigned* a, const unsigned* b) {
    asm volatile("mma.sync.aligned.m16n8k16.row.col.f32.bf16.bf16.f32 "
                 "{%0,%1,%2,%3}, {%4,%5,%6,%7}, {%8,%9}, {%0,%1,%2,%3};"
                 : "+f"(c[0]), "+f"(c[1]), "+f"(c[2]), "+f"(c[3])
                 : "r"(a[0]), "r"(a[1]), "r"(a[2]), "r"(a[3]), "r"(b[0]), "r"(b[1]));
}
__device__ __forceinline__ void split2(float x, __nv_bfloat16& a, __nv_bfloat16& b) {
    a = __float2bfloat16_rn(x);
    b = __float2bfloat16_rn(x - __bfloat162float(a));
}
__device__ __forceinline__ unsigned f2key(float f) {
    unsigned u = __float_as_uint(f);
    return (u & 0x80000000u) ? ~u : (u | 0x80000000u);
}
__device__ __forceinline__ float key2f(unsigned u) {
    unsigned b = (u & 0x80000000u) ? (u & 0x7FFFFFFFu) : ~u;
    return __uint_as_float(b);
}
// byte offset of element (row rb in tile, k kin in chunk) inside a swizzled 16KB tile
__device__ __forceinline__ size_t tile_off(int rb, int kin) {
    return (size_t)(rb * 128 + ((((unsigned)kin >> 3) ^ (rb & 7)) << 4) + (kin & 7) * 2);
}

// boundary-bucket search: warp 0 computes (bucket, remaining k) from hist for krem
__device__ __forceinline__ void radix_boundary(int* hist, int krem, int* st, int tid) {
    if (tid < 32) {
        int ll = tid;
        int s = 0;
#pragma unroll
        for (int k = 0; k < 8; k++) s += hist[255 - (ll * 8 + k)];
        int cum = s;
#pragma unroll
        for (int off = 1; off < 32; off <<= 1) {
            int v = __shfl_up_sync(0xffffffffu, cum, off);
            if (ll >= off) cum += v;
        }
        unsigned ball = __ballot_sync(0xffffffffu, cum >= krem);
        int lstar = __ffs(ball) - 1;
        if (ll == lstar) {
            int cacc = cum - s;
            int bsel = 0, nk = krem;
#pragma unroll
            for (int k = 0; k < 8; k++) {
                int bkt = 255 - (ll * 8 + k);
                int h = hist[bkt];
                if (cacc + h >= krem) { bsel = bkt; nk = krem - cacc; break; }
                cacc += h;
            }
            st[0] = bsel; st[1] = nk;
        }
    }
}

__global__ void reset_kernel() { g_nrisky = 0; }

// ============ kernel 1: conv+bn+relu+maxpool -> fp32 h + swizzled bf16 split tiles ============
__global__ __launch_bounds__(320) void conv_pool_kernel(
    const float* __restrict__ x, const float* __restrict__ conv_w,
    const float* __restrict__ gamma, const float* __restrict__ beta,
    const float* __restrict__ mean, const float* __restrict__ var,
    const float* __restrict__ fc_w)
{
    __shared__ float img[784];
    int b = blockIdx.x;
    int t = threadIdx.x;

    int kc = t / 64, kin = t - kc * 64;

    if (b < EMB) {   // fc_w row b -> swizzled B split tiles (fc_w is [EMB][FEAT], K-major)
        float wv = fc_w[b * FEAT + t];
        __nv_bfloat16 w1, w2; split2(wv, w1, w2);
        size_t off = ((size_t)((b >> 7) * NCHUNK + kc)) * TILE_B + tile_off(b & 127, kin);
        *(__nv_bfloat16*)(g_Bw[0] + off) = w1;
        *(__nv_bfloat16*)(g_Bw[1] + off) = w2;
    }

    const float* xb = x + (size_t)b * 784;
    for (int i = t; i < 784; i += 320) img[i] = xb[i];

    int c = t >> 6, r = t & 63, py = r >> 3, px = r & 7;
    float w[9];
#pragma unroll
    for (int i = 0; i < 9; i++) w[i] = __ldg(&conv_w[c * 9 + i]);
    float s  = __ldg(&gamma[c]) / sqrtf(__ldg(&var[c]) + 1e-5f);
    float bb = __ldg(&beta[c]) - __ldg(&mean[c]) * s;
    __syncthreads();

    int y0 = py * 3, x0 = px * 3;
    float m = -3.402823466e38f;
#pragma unroll
    for (int dy = 0; dy < 3; dy++)
#pragma unroll
    for (int dx = 0; dx < 3; dx++) {
        float acc = 0.f;
#pragma unroll
        for (int i = 0; i < 3; i++)
#pragma unroll
        for (int j = 0; j < 3; j++)
            acc = fmaf(img[(y0 + dy + i) * 28 + x0 + dx + j], w[i * 3 + j], acc);
        m = fmaxf(m, fmaf(acc, s, bb));
    }
    m = fmaxf(m, 0.f);
    g_hf[(size_t)b * FEAT + t] = m;
    __nv_bfloat16 a1, a2; split2(m, a1, a2);
    size_t off = ((size_t)((b >> 7) * NCHUNK + kc)) * TILE_B + tile_off(b & 127, kin);
    *(__nv_bfloat16*)(g_Aw[0] + off) = a1;
    *(__nv_bfloat16*)(g_Aw[1] + off) = a2;
}

// ============ kernel 2: bulk-copy pipelined mma.sync 3-term split GEMM -> z keys ============
// R11-proven skeleton (256 thr, 8 warps 4x2, 32x64 warp tiles, ldsm2 B loads);
// ONLY change vs R11: products {21,12,11} (a2*b2 dropped; covered by MARGIN_MIN+fixup)
__global__ __launch_bounds__(256, 1) void gemm_kernel(int cta_base)
{
    extern __shared__ char smem[];
    const unsigned sbase = smem_u32(smem);
    const unsigned mb = sbase + 3 * STAGE_B;        // 3 mbarriers
    const int tid = threadIdx.x;
    const int wid = tid >> 5, l = tid & 31;
    const int wm = wid & 3;          // warp m-tile (32 rows)
    const int wn = wid >> 2;         // warp n-tile (64 cols)
    const int bx = blockIdx.x + cta_base;
    const int mt  = bx >> 4;
    const int nt0 = bx & 15;

    if (tid == 0) {
        mbar_init(mb + 0, 1); mbar_init(mb + 8, 1); mbar_init(mb + 16, 1);
        asm volatile("fence.proxy.async.shared::cta;" ::: "memory");
    }
    __syncthreads();

    auto issue = [&](int s) {
        unsigned slot = sbase + (s % 3) * STAGE_B;
        unsigned m = mb + (s % 3) * 8;
        mbar_expect_tx(m, STAGE_B);
        bulkcp(slot,             g_Aw[0] + ((size_t)(mt  * NCHUNK + s)) * TILE_B, TILE_B, m);
        bulkcp(slot + TILE_B,    g_Aw[1] + ((size_t)(mt  * NCHUNK + s)) * TILE_B, TILE_B, m);
        bulkcp(slot + 2*TILE_B,  g_Bw[0] + ((size_t)(nt0 * NCHUNK + s)) * TILE_B, TILE_B, m);
        bulkcp(slot + 3*TILE_B,  g_Bw[1] + ((size_t)(nt0 * NCHUNK + s)) * TILE_B, TILE_B, m);
    };
    if (tid == 0) { issue(0); issue(1); issue(2); }

    float acc[2][8][4];
#pragma unroll
    for (int mh = 0; mh < 2; mh++)
#pragma unroll
        for (int nt = 0; nt < 8; nt++)
#pragma unroll
            for (int v = 0; v < 4; v++) acc[mh][nt][v] = 0.f;

    const unsigned s7 = l & 7;
    const unsigned aoff = (wm * 32 + (l & 15)) * 128;
    const unsigned boff = (wn * 64 + (l & 7)) * 128;
    const unsigned au = l >> 4;
    const unsigned bu = (l >> 3) & 1;

    for (int s = 0; s < NCHUNK; s++) {
        mbar_wait(mb + (s % 3) * 8, (s < 3) ? 0 : 1);
        unsigned base = sbase + (s % 3) * STAGE_B;
#pragma unroll
        for (int kk = 0; kk < 4; kk++) {
            unsigned ua = ((2 * kk + au) ^ s7) << 4;
            unsigned ub = ((2 * kk + bu) ^ s7) << 4;
            unsigned As[2][2][4], Bs[2][8][2];
#pragma unroll
            for (int sp = 0; sp < 2; sp++) {
                unsigned Ab = base + sp * TILE_B + aoff + ua;
                ldsm4(As[sp][0][0], As[sp][0][1], As[sp][0][2], As[sp][0][3], Ab);
                ldsm4(As[sp][1][0], As[sp][1][1], As[sp][1][2], As[sp][1][3], Ab + 2048);
                unsigned Bb = base + 2 * TILE_B + sp * TILE_B + boff + ub;
#pragma unroll
                for (int nt = 0; nt < 8; nt++)
                    ldsm2(Bs[sp][nt][0], Bs[sp][nt][1], Bb + nt * 1024);
            }
            // products smallest-first: (A1,B0) (A0,B1) (A0,B0)
#pragma unroll
            for (int p = 0; p < 3; p++) {
                const int ia = (p == 0) ? 1 : 0;
                const int ib = (p == 1) ? 1 : 0;
#pragma unroll
                for (int nt = 0; nt < 8; nt++) {
                    mma16816(acc[0][nt], As[ia][0], Bs[ib][nt]);
                    mma16816(acc[1][nt], As[ia][1], Bs[ib][nt]);
                }
            }
        }
        __syncthreads();
        if (tid == 0 && s + 3 < NCHUNK) issue(s + 3);
    }

    // ---- epilogue: keys, smem transpose, coalesced store ----
    unsigned* sz = (unsigned*)smem;          // [128][132]
#pragma unroll
    for (int mh = 0; mh < 2; mh++)
#pragma unroll
        for (int nt = 0; nt < 8; nt++)
#pragma unroll
            for (int v = 0; v < 4; v++) {
                int row = wm * 32 + mh * 16 + (l >> 2) + ((v >> 1) << 3);
                int col = wn * 64 + nt * 8 + 2 * (l & 3) + (v & 1);
                sz[row * 132 + col] = f2key(acc[mh][nt][v]);
            }
    __syncthreads();

    unsigned* dst = g_z + (size_t)mt * TM * EMB + nt0 * TN;
#pragma unroll 8
    for (int i = 0; i < 64; i++) {
        int idx = i * 256 + tid;
        int r = idx >> 7, c = idx & 127;
        dst[(size_t)r * EMB + c] = sz[r * 132 + c];
    }
}

// ============ kernel 3: per-row radix top-k + binarize + risky detection (R8-proven) ============
__global__ __launch_bounds__(256) void select_kernel(float* __restrict__ out)
{
    __shared__ unsigned keys[EMB];
    __shared__ int hist[256];
    __shared__ int st[2];
    __shared__ unsigned red[16];
    int tid = threadIdx.x;
    int row = blockIdx.x;
    int wid = tid >> 5, l = tid & 31;

    const uint4* src = (const uint4*)(g_z + (size_t)row * EMB);
    ((uint4*)keys)[tid]       = src[tid];
    ((uint4*)keys)[tid + 256] = src[tid + 256];
    __syncthreads();

    int krem = KACT; unsigned prefix = 0, mask = 0;
    for (int pass = 0; pass < 4; pass++) {
        int shift = 24 - 8 * pass;
        hist[tid] = 0;
        __syncthreads();
        for (int i = tid; i < EMB; i += 256) {
            unsigned u = keys[i];
            if ((u & mask) == prefix) atomicAdd(&hist[(u >> shift) & 255], 1);
        }
        __syncthreads();
        radix_boundary(hist, krem, st, tid);
        __syncthreads();
        prefix |= ((unsigned)st[0]) << shift;
        krem = st[1];
        mask |= 0xFFu << shift;
    }

    // binarize + margin + tie count (single fused scan)
    unsigned thr = prefix;
    unsigned second = 0; int cnt = 0;
    float* o = out + (size_t)row * EMB;
#pragma unroll
    for (int i = 0; i < 8; i++) {
        unsigned u = keys[tid + i * 256];
        bool in = (u >= thr);
        o[tid + i * 256] = in ? 1.0f : 0.0f;
        if (in) cnt++;
        else if (u > second) second = u;
    }
#pragma unroll
    for (int off = 16; off; off >>= 1) {
        unsigned os = __shfl_xor_sync(0xffffffffu, second, off);
        if (os > second) second = os;
        cnt += __shfl_xor_sync(0xffffffffu, cnt, off);
    }
    if (l == 0) { red[wid] = second; red[8 + wid] = (unsigned)cnt; }
    __syncthreads();
    if (tid == 0) {
        unsigned s2 = 0; int ct = 0;
#pragma unroll
        for (int w = 0; w < 8; w++) { s2 = max(s2, red[w]); ct += (int)red[8 + w]; }
        float margin = key2f(thr) - key2f(s2);
        if (ct != KACT || !(margin > MARGIN_MIN)) {
            int p = atomicAdd(&g_nrisky, 1);
            g_risky[p] = row;
        }
    }
}

// ============ kernel 4: exact fixup, FAST (8 col-chains/thread, float4 w loads) ============
// per-column k-order is strictly sequential 0..319 -> bitwise-matches reference fp32 path
__global__ __launch_bounds__(256) void fixup_kernel(const float* __restrict__ fc_w,
                                                    float* __restrict__ out)
{
    __shared__ float hrow[FEAT];
    __shared__ unsigned keys[EMB];
    __shared__ int hist[256];
    __shared__ int st[2];
    int tid = threadIdx.x;
    int n = *(volatile int*)&g_nrisky;

    for (int it = blockIdx.x; it < n; it += gridDim.x) {
        int row = g_risky[it];
        for (int i = tid; i < FEAT; i += 256) hrow[i] = g_hf[(size_t)row * FEAT + i];
        __syncthreads();

        float acc[8];
#pragma unroll
        for (int c = 0; c < 8; c++) acc[c] = 0.f;
        const float4* w4 = (const float4*)fc_w;       // row pitch = 80 float4
#pragma unroll 4
        for (int k4 = 0; k4 < FEAT / 4; k4++) {
            float4 h4 = ((const float4*)hrow)[k4];
            float4 wv[8];
#pragma unroll
            for (int c = 0; c < 8; c++)
                wv[c] = w4[(size_t)(c * 256 + tid) * (FEAT / 4) + k4];
#pragma unroll
            for (int c = 0; c < 8; c++) {
                acc[c] = fmaf(h4.x, wv[c].x, acc[c]);
                acc[c] = fmaf(h4.y, wv[c].y, acc[c]);
                acc[c] = fmaf(h4.z, wv[c].z, acc[c]);
                acc[c] = fmaf(h4.w, wv[c].w, acc[c]);
            }
        }
#pragma unroll
        for (int c = 0; c < 8; c++) keys[c * 256 + tid] = f2key(acc[c]);
        __syncthreads();

        int krem = KACT; unsigned prefix = 0, mask = 0;
        for (int pass = 0; pass < 4; pass++) {
            int shift = 24 - 8 * pass;
            hist[tid] = 0;
            __syncthreads();
            for (int i = tid; i < EMB; i += 256) {
                unsigned u = keys[i];
                if ((u & mask) == prefix) atomicAdd(&hist[(u >> shift) & 255], 1);
            }
            __syncthreads();
            radix_boundary(hist, krem, st, tid);
            __syncthreads();
            prefix |= ((unsigned)st[0]) << shift;
            krem = st[1];
            mask |= 0xFFu << shift;
        }

        float* outp = out + (size_t)row * EMB;
        for (int i = tid; i < EMB; i += 256) outp[i] = (keys[i] >= prefix) ? 1.0f : 0.0f;
        __syncthreads();
    }
}

// ============ launch ============
extern "C" void kernel_launch(void* const* d_in, const int* in_sizes, int n_in,
                              void* d_out, int out_size)
{
    const float* x      = (const float*)d_in[0];
    const float* conv_w = (const float*)d_in[1];
    const float* gamma  = (const float*)d_in[2];
    const float* beta   = (const float*)d_in[3];
    const float* mean   = (const float*)d_in[4];
    const float* var    = (const float*)d_in[5];
    const float* fc_w   = (const float*)d_in[6];
    float* out = (float*)d_out;

    cudaFuncSetAttribute(gemm_kernel, cudaFuncAttributeMaxDynamicSharedMemorySize, SMEM_GEMM);

    const int NCTA = (BATCH / TM) * (EMB / TN);    // 4096
    reset_kernel<<<1, 1>>>();
    conv_pool_kernel<<<BATCH, 320>>>(x, conv_w, gamma, beta, mean, var, fc_w);
    gemm_kernel<<<NCTA / 2, 256, SMEM_GEMM>>>(0);
    gemm_kernel<<<NCTA / 2, 256, SMEM_GEMM>>>(NCTA / 2);
    select_kernel<<<BATCH, 256>>>(out);
    fixup_kernel<<<1024, 256>>>(fc_w, out);
}

// round 13
// speedup vs baseline: 1.1934x; 1.1934x over previous
#include <cuda_runtime.h>
#include <cuda_bf16.h>

#define BATCH 32768
#define EMB   2048
#define FEAT  320
#define KACT  103          // ceil(0.05*2048)
#define MARGIN_MIN 4e-5f   // > 2*(|z_fast-z_exact| + |z_ref-z_exact|) bound (4-product split)

// ---- GEMM tiling ----
#define TM 128
#define TN 128
#define NCHUNK 5           // FEAT / 64
#define TILE_B 16384       // one split tile: 128 rows x 128B (swizzled)
#define STAGE_B 65536      // A0,A1,B0,B1
#define SMEM_GEMM (3*STAGE_B + 64)   // 196672; epilogue reuse 128*132*4=67584 fits

// ---- device scratch (no allocs allowed) ----
// pre-swizzled tiled splits: [split][(tile*NCHUNK + chunk)*16KB]
__device__ __align__(16) char g_Aw[2][(BATCH/128) * NCHUNK * TILE_B];  // 2 x 20 MB
__device__ __align__(16) char g_Bw[2][(EMB/128)   * NCHUNK * TILE_B];  // 2 x 1.25 MB
__device__ float    g_hf[BATCH * FEAT];        // exact fp32 h for fixup, 42 MB
__device__ unsigned g_z[(size_t)BATCH * EMB];  // order-preserving z keys, 268 MB
__device__ int      g_nrisky;
__device__ int      g_risky[BATCH];

// ================= helpers =================
__device__ __forceinline__ unsigned smem_u32(const void* p) {
    unsigned a;
    asm("{ .reg .u64 t; cvta.to.shared.u64 t, %1; cvt.u32.u64 %0, t; }" : "=r"(a) : "l"(p));
    return a;
}
__device__ __forceinline__ void mbar_init(unsigned a, unsigned cnt) {
    asm volatile("mbarrier.init.shared.b64 [%0], %1;" :: "r"(a), "r"(cnt) : "memory");
}
__device__ __forceinline__ void mbar_expect_tx(unsigned a, unsigned bytes) {
    asm volatile("mbarrier.arrive.expect_tx.shared.b64 _, [%0], %1;" :: "r"(a), "r"(bytes) : "memory");
}
__device__ __forceinline__ void mbar_wait(unsigned a, unsigned parity) {
    asm volatile("{\n\t.reg .pred P;\n\tWL_%=:\n\t"
                 "mbarrier.try_wait.parity.acquire.cta.shared::cta.b64 P, [%0], %1, 0x989680;\n\t"
                 "@P bra.uni WD_%=;\n\tbra.uni WL_%=;\n\tWD_%=:\n\t}"
                 :: "r"(a), "r"(parity) : "memory");
}
__device__ __forceinline__ void bulkcp(unsigned dsmem, const void* gsrc, unsigned bytes, unsigned mbar) {
    asm volatile("cp.async.bulk.shared::cluster.global.mbarrier::complete_tx::bytes "
                 "[%0], [%1], %2, [%3];"
                 :: "r"(dsmem), "l"(gsrc), "r"(bytes), "r"(mbar) : "memory");
}
__device__ __forceinline__ void ldsm4(unsigned& r0, unsigned& r1, unsigned& r2, unsigned& r3, unsigned a) {
    asm volatile("ldmatrix.sync.aligned.m8n8.x4.shared.b16 {%0,%1,%2,%3}, [%4];"
                 : "=r"(r0), "=r"(r1), "=r"(r2), "=r"(r3) : "r"(a));
}
__device__ __forceinline__ void ldsm2(unsigned& r0, unsigned& r1, unsigned a) {
    asm volatile("ldmatrix.sync.aligned.m8n8.x2.shared.b16 {%0,%1}, [%2];"
                 : "=r"(r0), "=r"(r1) : "r"(a));
}
__device__ __forceinline__ void mma16816(float* c, const unsigned* a, const unsigned* b) {
    asm volatile("mma.sync.aligned.m16n8k16.row.col.f32.bf16.bf16.f32 "
                 "{%0,%1,%2,%3}, {%4,%5,%6,%7}, {%8,%9}, {%0,%1,%2,%3};"
                 : "+f"(c[0]), "+f"(c[1]), "+f"(c[2]), "+f"(c[3])
                 : "r"(a[0]), "r"(a[1]), "r"(a[2]), "r"(a[3]), "r"(b[0]), "r"(b[1]));
}
__device__ __forceinline__ void split2(float x, __nv_bfloat16& a, __nv_bfloat16& b) {
    a = __float2bfloat16_rn(x);
    b = __float2bfloat16_rn(x - __bfloat162float(a));
}
__device__ __forceinline__ unsigned f2key(float f) {
    unsigned u = __float_as_uint(f);
    return (u & 0x80000000u) ? ~u : (u | 0x80000000u);
}
__device__ __forceinline__ float key2f(unsigned u) {
    unsigned b = (u & 0x80000000u) ? (u & 0x7FFFFFFFu) : ~u;
    return __uint_as_float(b);
}
// byte offset of element (row rb in tile, k kin in chunk) inside a swizzled 16KB tile
__device__ __forceinline__ size_t tile_off(int rb, int kin) {
    return (size_t)(rb * 128 + ((((unsigned)kin >> 3) ^ (rb & 7)) << 4) + (kin & 7) * 2);
}

// boundary-bucket search: warp 0 computes (bucket, remaining k) from hist for krem
__device__ __forceinline__ void radix_boundary(int* hist, int krem, int* st, int tid) {
    if (tid < 32) {
        int ll = tid;
        int s = 0;
#pragma unroll
        for (int k = 0; k < 8; k++) s += hist[255 - (ll * 8 + k)];
        int cum = s;
#pragma unroll
        for (int off = 1; off < 32; off <<= 1) {
            int v = __shfl_up_sync(0xffffffffu, cum, off);
            if (ll >= off) cum += v;
        }
        unsigned ball = __ballot_sync(0xffffffffu, cum >= krem);
        int lstar = __ffs(ball) - 1;
        if (ll == lstar) {
            int cacc = cum - s;
            int bsel = 0, nk = krem;
#pragma unroll
            for (int k = 0; k < 8; k++) {
                int bkt = 255 - (ll * 8 + k);
                int h = hist[bkt];
                if (cacc + h >= krem) { bsel = bkt; nk = krem - cacc; break; }
                cacc += h;
            }
            st[0] = bsel; st[1] = nk;
        }
    }
}

__global__ void reset_kernel() { g_nrisky = 0; }

// ============ kernel 1: conv+bn+relu+maxpool, 4 images/block -> fp32 h + swizzled splits ============
#define IMGS 4
__global__ __launch_bounds__(320) void conv_pool_kernel(
    const float* __restrict__ x, const float* __restrict__ conv_w,
    const float* __restrict__ gamma, const float* __restrict__ beta,
    const float* __restrict__ mean, const float* __restrict__ var,
    const float* __restrict__ fc_w)
{
    __shared__ float img[IMGS * 784];
    int blk = blockIdx.x;
    int b0 = blk * IMGS;
    int t = threadIdx.x;

    int kc = t / 64, kin = t - kc * 64;

    if (blk < EMB) {   // fc_w row blk -> swizzled B split tiles (fc_w is [EMB][FEAT], K-major)
        float wv = fc_w[blk * FEAT + t];
        __nv_bfloat16 w1, w2; split2(wv, w1, w2);
        size_t off = ((size_t)((blk >> 7) * NCHUNK + kc)) * TILE_B + tile_off(blk & 127, kin);
        *(__nv_bfloat16*)(g_Bw[0] + off) = w1;
        *(__nv_bfloat16*)(g_Bw[1] + off) = w2;
    }

    const float* xb = x + (size_t)b0 * 784;
    for (int i = t; i < IMGS * 784; i += 320) img[i] = xb[i];

    int c = t >> 6, r = t & 63, py = r >> 3, px = r & 7;
    float w[9];
#pragma unroll
    for (int i = 0; i < 9; i++) w[i] = __ldg(&conv_w[c * 9 + i]);
    float s  = __ldg(&gamma[c]) / sqrtf(__ldg(&var[c]) + 1e-5f);
    float bb = __ldg(&beta[c]) - __ldg(&mean[c]) * s;
    __syncthreads();

    int y0 = py * 3, x0 = px * 3;
#pragma unroll
    for (int im = 0; im < IMGS; im++) {
        const float* ip = img + im * 784;
        float m = -3.402823466e38f;
#pragma unroll
        for (int dy = 0; dy < 3; dy++)
#pragma unroll
        for (int dx = 0; dx < 3; dx++) {
            float acc = 0.f;
#pragma unroll
            for (int i = 0; i < 3; i++)
#pragma unroll
            for (int j = 0; j < 3; j++)
                acc = fmaf(ip[(y0 + dy + i) * 28 + x0 + dx + j], w[i * 3 + j], acc);
            m = fmaxf(m, fmaf(acc, s, bb));
        }
        m = fmaxf(m, 0.f);
        int b = b0 + im;
        g_hf[(size_t)b * FEAT + t] = m;
        __nv_bfloat16 a1, a2; split2(m, a1, a2);
        size_t off = ((size_t)((b >> 7) * NCHUNK + kc)) * TILE_B + tile_off(b & 127, kin);
        *(__nv_bfloat16*)(g_Aw[0] + off) = a1;
        *(__nv_bfloat16*)(g_Aw[1] + off) = a2;
    }
}

// ============ kernel 2: bulk-copy pipelined mma.sync 4-term split GEMM -> z keys ============
// R11-proven (879us): 256 thr, 8 warps 4x2, 32x64 warp tiles, ldsm2 B loads,
// products smallest-first (A1,B1)(A1,B0)(A0,B1)(A0,B0)
__global__ __launch_bounds__(256, 1) void gemm_kernel(int cta_base)
{
    extern __shared__ char smem[];
    const unsigned sbase = smem_u32(smem);
    const unsigned mb = sbase + 3 * STAGE_B;        // 3 mbarriers
    const int tid = threadIdx.x;
    const int wid = tid >> 5, l = tid & 31;
    const int wm = wid & 3;          // warp m-tile (32 rows)
    const int wn = wid >> 2;         // warp n-tile (64 cols)
    const int bx = blockIdx.x + cta_base;
    const int mt  = bx >> 4;
    const int nt0 = bx & 15;

    if (tid == 0) {
        mbar_init(mb + 0, 1); mbar_init(mb + 8, 1); mbar_init(mb + 16, 1);
        asm volatile("fence.proxy.async.shared::cta;" ::: "memory");
    }
    __syncthreads();

    auto issue = [&](int s) {
        unsigned slot = sbase + (s % 3) * STAGE_B;
        unsigned m = mb + (s % 3) * 8;
        mbar_expect_tx(m, STAGE_B);
        bulkcp(slot,             g_Aw[0] + ((size_t)(mt  * NCHUNK + s)) * TILE_B, TILE_B, m);
        bulkcp(slot + TILE_B,    g_Aw[1] + ((size_t)(mt  * NCHUNK + s)) * TILE_B, TILE_B, m);
        bulkcp(slot + 2*TILE_B,  g_Bw[0] + ((size_t)(nt0 * NCHUNK + s)) * TILE_B, TILE_B, m);
        bulkcp(slot + 3*TILE_B,  g_Bw[1] + ((size_t)(nt0 * NCHUNK + s)) * TILE_B, TILE_B, m);
    };
    if (tid == 0) { issue(0); issue(1); issue(2); }

    float acc[2][8][4];
#pragma unroll
    for (int mh = 0; mh < 2; mh++)
#pragma unroll
        for (int nt = 0; nt < 8; nt++)
#pragma unroll
            for (int v = 0; v < 4; v++) acc[mh][nt][v] = 0.f;

    const unsigned s7 = l & 7;
    const unsigned aoff = (wm * 32 + (l & 15)) * 128;
    const unsigned boff = (wn * 64 + (l & 7)) * 128;
    const unsigned au = l >> 4;
    const unsigned bu = (l >> 3) & 1;

    for (int s = 0; s < NCHUNK; s++) {
        mbar_wait(mb + (s % 3) * 8, (s < 3) ? 0 : 1);
        unsigned base = sbase + (s % 3) * STAGE_B;
#pragma unroll
        for (int kk = 0; kk < 4; kk++) {
            unsigned ua = ((2 * kk + au) ^ s7) << 4;
            unsigned ub = ((2 * kk + bu) ^ s7) << 4;
            unsigned As[2][2][4], Bs[2][8][2];
#pragma unroll
            for (int sp = 0; sp < 2; sp++) {
                unsigned Ab = base + sp * TILE_B + aoff + ua;
                ldsm4(As[sp][0][0], As[sp][0][1], As[sp][0][2], As[sp][0][3], Ab);
                ldsm4(As[sp][1][0], As[sp][1][1], As[sp][1][2], As[sp][1][3], Ab + 2048);
                unsigned Bb = base + 2 * TILE_B + sp * TILE_B + boff + ub;
#pragma unroll
                for (int nt = 0; nt < 8; nt++)
                    ldsm2(Bs[sp][nt][0], Bs[sp][nt][1], Bb + nt * 1024);
            }
            // products smallest-first: (A1,B1) (A1,B0) (A0,B1) (A0,B0)
#pragma unroll
            for (int p = 0; p < 4; p++) {
                const int ia = (p < 2) ? 1 : 0;
                const int ib = ((p & 1) == 0) ? 1 : 0;
#pragma unroll
                for (int nt = 0; nt < 8; nt++) {
                    mma16816(acc[0][nt], As[ia][0], Bs[ib][nt]);
                    mma16816(acc[1][nt], As[ia][1], Bs[ib][nt]);
                }
            }
        }
        __syncthreads();
        if (tid == 0 && s + 3 < NCHUNK) issue(s + 3);
    }

    // ---- epilogue: keys, smem transpose, coalesced store ----
    unsigned* sz = (unsigned*)smem;          // [128][132]
#pragma unroll
    for (int mh = 0; mh < 2; mh++)
#pragma unroll
        for (int nt = 0; nt < 8; nt++)
#pragma unroll
            for (int v = 0; v < 4; v++) {
                int row = wm * 32 + mh * 16 + (l >> 2) + ((v >> 1) << 3);
                int col = wn * 64 + nt * 8 + 2 * (l & 3) + (v & 1);
                sz[row * 132 + col] = f2key(acc[mh][nt][v]);
            }
    __syncthreads();

    unsigned* dst = g_z + (size_t)mt * TM * EMB + nt0 * TN;
#pragma unroll 8
    for (int i = 0; i < 64; i++) {
        int idx = i * 256 + tid;
        int r = idx >> 7, c = idx & 127;
        dst[(size_t)r * EMB + c] = sz[r * 132 + c];
    }
}

// ============ kernel 3: per-row radix top-k + binarize + risky detection (proven) ============
__global__ __launch_bounds__(256) void select_kernel(float* __restrict__ out)
{
    __shared__ unsigned keys[EMB];
    __shared__ int hist[256];
    __shared__ int st[2];
    __shared__ unsigned red[16];
    int tid = threadIdx.x;
    int row = blockIdx.x;
    int wid = tid >> 5, l = tid & 31;

    const uint4* src = (const uint4*)(g_z + (size_t)row * EMB);
    ((uint4*)keys)[tid]       = src[tid];
    ((uint4*)keys)[tid + 256] = src[tid + 256];
    __syncthreads();

    int krem = KACT; unsigned prefix = 0, mask = 0;
    for (int pass = 0; pass < 4; pass++) {
        int shift = 24 - 8 * pass;
        hist[tid] = 0;
        __syncthreads();
        for (int i = tid; i < EMB; i += 256) {
            unsigned u = keys[i];
            if ((u & mask) == prefix) atomicAdd(&hist[(u >> shift) & 255], 1);
        }
        __syncthreads();
        radix_boundary(hist, krem, st, tid);
        __syncthreads();
        prefix |= ((unsigned)st[0]) << shift;
        krem = st[1];
        mask |= 0xFFu << shift;
    }

    // binarize + margin + tie count (single fused scan)
    unsigned thr = prefix;
    unsigned second = 0; int cnt = 0;
    float* o = out + (size_t)row * EMB;
#pragma unroll
    for (int i = 0; i < 8; i++) {
        unsigned u = keys[tid + i * 256];
        bool in = (u >= thr);
        o[tid + i * 256] = in ? 1.0f : 0.0f;
        if (in) cnt++;
        else if (u > second) second = u;
    }
#pragma unroll
    for (int off = 16; off; off >>= 1) {
        unsigned os = __shfl_xor_sync(0xffffffffu, second, off);
        if (os > second) second = os;
        cnt += __shfl_xor_sync(0xffffffffu, cnt, off);
    }
    if (l == 0) { red[wid] = second; red[8 + wid] = (unsigned)cnt; }
    __syncthreads();
    if (tid == 0) {
        unsigned s2 = 0; int ct = 0;
#pragma unroll
        for (int w = 0; w < 8; w++) { s2 = max(s2, red[w]); ct += (int)red[8 + w]; }
        float margin = key2f(thr) - key2f(s2);
        if (ct != KACT || !(margin > MARGIN_MIN)) {
            int p = atomicAdd(&g_nrisky, 1);
            g_risky[p] = row;
        }
    }
}

// ============ kernel 4: exact fixup, FAST (8 col-chains/thread, float4 w loads) ============
// per-column k-order is strictly sequential 0..319 -> bitwise-matches reference fp32 path
__global__ __launch_bounds__(256) void fixup_kernel(const float* __restrict__ fc_w,
                                                    float* __restrict__ out)
{
    __shared__ float hrow[FEAT];
    __shared__ unsigned keys[EMB];
    __shared__ int hist[256];
    __shared__ int st[2];
    int tid = threadIdx.x;
    int n = *(volatile int*)&g_nrisky;

    for (int it = blockIdx.x; it < n; it += gridDim.x) {
        int row = g_risky[it];
        for (int i = tid; i < FEAT; i += 256) hrow[i] = g_hf[(size_t)row * FEAT + i];
        __syncthreads();

        float acc[8];
#pragma unroll
        for (int c = 0; c < 8; c++) acc[c] = 0.f;
        const float4* w4 = (const float4*)fc_w;       // row pitch = 80 float4
#pragma unroll 4
        for (int k4 = 0; k4 < FEAT / 4; k4++) {
            float4 h4 = ((const float4*)hrow)[k4];
            float4 wv[8];
#pragma unroll
            for (int c = 0; c < 8; c++)
                wv[c] = w4[(size_t)(c * 256 + tid) * (FEAT / 4) + k4];
#pragma unroll
            for (int c = 0; c < 8; c++) {
                acc[c] = fmaf(h4.x, wv[c].x, acc[c]);
                acc[c] = fmaf(h4.y, wv[c].y, acc[c]);
                acc[c] = fmaf(h4.z, wv[c].z, acc[c]);
                acc[c] = fmaf(h4.w, wv[c].w, acc[c]);
            }
        }
#pragma unroll
        for (int c = 0; c < 8; c++) keys[c * 256 + tid] = f2key(acc[c]);
        __syncthreads();

        int krem = KACT; unsigned prefix = 0, mask = 0;
        for (int pass = 0; pass < 4; pass++) {
            int shift = 24 - 8 * pass;
            hist[tid] = 0;
            __syncthreads();
            for (int i = tid; i < EMB; i += 256) {
                unsigned u = keys[i];
                if ((u & mask) == prefix) atomicAdd(&hist[(u >> shift) & 255], 1);
            }
            __syncthreads();
            radix_boundary(hist, krem, st, tid);
            __syncthreads();
            prefix |= ((unsigned)st[0]) << shift;
            krem = st[1];
            mask |= 0xFFu << shift;
        }

        float* outp = out + (size_t)row * EMB;
        for (int i = tid; i < EMB; i += 256) outp[i] = (keys[i] >= prefix) ? 1.0f : 0.0f;
        __syncthreads();
    }
}

// ============ launch ============
extern "C" void kernel_launch(void* const* d_in, const int* in_sizes, int n_in,
                              void* d_out, int out_size)
{
    const float* x      = (const float*)d_in[0];
    const float* conv_w = (const float*)d_in[1];
    const float* gamma  = (const float*)d_in[2];
    const float* beta   = (const float*)d_in[3];
    const float* mean   = (const float*)d_in[4];
    const float* var    = (const float*)d_in[5];
    const float* fc_w   = (const float*)d_in[6];
    float* out = (float*)d_out;

    cudaFuncSetAttribute(gemm_kernel, cudaFuncAttributeMaxDynamicSharedMemorySize, SMEM_GEMM);

    const int NCTA = (BATCH / TM) * (EMB / TN);    // 4096
    reset_kernel<<<1, 1>>>();
    conv_pool_kernel<<<BATCH / IMGS, 320>>>(x, conv_w, gamma, beta, mean, var, fc_w);
    gemm_kernel<<<NCTA / 2, 256, SMEM_GEMM>>>(0);
    gemm_kernel<<<NCTA / 2, 256, SMEM_GEMM>>>(NCTA / 2);
    select_kernel<<<BATCH, 256>>>(out);
    fixup_kernel<<<1024, 256>>>(fc_w, out);
}

// round 14
// speedup vs baseline: 1.2504x; 1.0477x over previous
#include <cuda_runtime.h>
#include <cuda_bf16.h>

#define BATCH 32768
#define EMB   2048
#define FEAT  320
#define KACT  103          // ceil(0.05*2048)
#define MARGIN_MIN 4e-5f   // > 2*(|z_fast-z_exact| + |z_ref-z_exact|) bound (4-product split)

// ---- GEMM tiling ----
#define TM 128
#define TN 128
#define NCHUNK 5           // FEAT / 64
#define NTILE  ((BATCH/TM)*(EMB/TN))   // 4096
#define GRID_P 148
#define TILE_B 16384       // one split tile: 128 rows x 128B (swizzled)
#define STAGE_B 65536      // A0,A1,B0,B1
#define SMEM_GEMM (3*STAGE_B + 64)   // 196672 (ring only; epilogue is direct-store)

// ---- device scratch (no allocs allowed) ----
// pre-swizzled tiled splits: [split][(tile*NCHUNK + chunk)*16KB]
__device__ __align__(16) char g_Aw[2][(BATCH/128) * NCHUNK * TILE_B];  // 2 x 20 MB
__device__ __align__(16) char g_Bw[2][(EMB/128)   * NCHUNK * TILE_B];  // 2 x 1.25 MB
__device__ float    g_hf[BATCH * FEAT];        // exact fp32 h for fixup, 42 MB
__device__ unsigned g_z[(size_t)BATCH * EMB];  // order-preserving z keys, 268 MB
__device__ int      g_nrisky;
__device__ int      g_risky[BATCH];

// ================= helpers =================
__device__ __forceinline__ unsigned smem_u32(const void* p) {
    unsigned a;
    asm("{ .reg .u64 t; cvta.to.shared.u64 t, %1; cvt.u32.u64 %0, t; }" : "=r"(a) : "l"(p));
    return a;
}
__device__ __forceinline__ void mbar_init(unsigned a, unsigned cnt) {
    asm volatile("mbarrier.init.shared.b64 [%0], %1;" :: "r"(a), "r"(cnt) : "memory");
}
__device__ __forceinline__ void mbar_expect_tx(unsigned a, unsigned bytes) {
    asm volatile("mbarrier.arrive.expect_tx.shared.b64 _, [%0], %1;" :: "r"(a), "r"(bytes) : "memory");
}
__device__ __forceinline__ void mbar_wait(unsigned a, unsigned parity) {
    asm volatile("{\n\t.reg .pred P;\n\tWL_%=:\n\t"
                 "mbarrier.try_wait.parity.acquire.cta.shared::cta.b64 P, [%0], %1, 0x989680;\n\t"
                 "@P bra.uni WD_%=;\n\tbra.uni WL_%=;\n\tWD_%=:\n\t}"
                 :: "r"(a), "r"(parity) : "memory");
}
__device__ __forceinline__ void bulkcp(unsigned dsmem, const void* gsrc, unsigned bytes, unsigned mbar) {
    asm volatile("cp.async.bulk.shared::cluster.global.mbarrier::complete_tx::bytes "
                 "[%0], [%1], %2, [%3];"
                 :: "r"(dsmem), "l"(gsrc), "r"(bytes), "r"(mbar) : "memory");
}
__device__ __forceinline__ void ldsm4(unsigned& r0, unsigned& r1, unsigned& r2, unsigned& r3, unsigned a) {
    asm volatile("ldmatrix.sync.aligned.m8n8.x4.shared.b16 {%0,%1,%2,%3}, [%4];"
                 : "=r"(r0), "=r"(r1), "=r"(r2), "=r"(r3) : "r"(a));
}
__device__ __forceinline__ void ldsm2(unsigned& r0, unsigned& r1, unsigned a) {
    asm volatile("ldmatrix.sync.aligned.m8n8.x2.shared.b16 {%0,%1}, [%2];"
                 : "=r"(r0), "=r"(r1) : "r"(a));
}
__device__ __forceinline__ void mma16816(float* c, const unsigned* a, const unsigned* b) {
    asm volatile("mma.sync.aligned.m16n8k16.row.col.f32.bf16.bf16.f32 "
                 "{%0,%1,%2,%3}, {%4,%5,%6,%7}, {%8,%9}, {%0,%1,%2,%3};"
                 : "+f"(c[0]), "+f"(c[1]), "+f"(c[2]), "+f"(c[3])
                 : "r"(a[0]), "r"(a[1]), "r"(a[2]), "r"(a[3]), "r"(b[0]), "r"(b[1]));
}
__device__ __forceinline__ void split2(float x, __nv_bfloat16& a, __nv_bfloat16& b) {
    a = __float2bfloat16_rn(x);
    b = __float2bfloat16_rn(x - __bfloat162float(a));
}
__device__ __forceinline__ unsigned f2key(float f) {
    unsigned u = __float_as_uint(f);
    return (u & 0x80000000u) ? ~u : (u | 0x80000000u);
}
__device__ __forceinline__ float key2f(unsigned u) {
    unsigned b = (u & 0x80000000u) ? (u & 0x7FFFFFFFu) : ~u;
    return __uint_as_float(b);
}
// byte offset of element (row rb in tile, k kin in chunk) inside a swizzled 16KB tile
__device__ __forceinline__ size_t tile_off(int rb, int kin) {
    return (size_t)(rb * 128 + ((((unsigned)kin >> 3) ^ (rb & 7)) << 4) + (kin & 7) * 2);
}

// boundary-bucket search: warp 0 computes (bucket, remaining k) from hist for krem
__device__ __forceinline__ void radix_boundary(int* hist, int krem, int* st, int tid) {
    if (tid < 32) {
        int ll = tid;
        int s = 0;
#pragma unroll
        for (int k = 0; k < 8; k++) s += hist[255 - (ll * 8 + k)];
        int cum = s;
#pragma unroll
        for (int off = 1; off < 32; off <<= 1) {
            int v = __shfl_up_sync(0xffffffffu, cum, off);
            if (ll >= off) cum += v;
        }
        unsigned ball = __ballot_sync(0xffffffffu, cum >= krem);
        int lstar = __ffs(ball) - 1;
        if (ll == lstar) {
            int cacc = cum - s;
            int bsel = 0, nk = krem;
#pragma unroll
            for (int k = 0; k < 8; k++) {
                int bkt = 255 - (ll * 8 + k);
                int h = hist[bkt];
                if (cacc + h >= krem) { bsel = bkt; nk = krem - cacc; break; }
                cacc += h;
            }
            st[0] = bsel; st[1] = nk;
        }
    }
}

__global__ void reset_kernel() { g_nrisky = 0; }

// ============ kernel 1: conv+bn+relu+maxpool, 4 images/block -> fp32 h + swizzled splits ============
#define IMGS 4
__global__ __launch_bounds__(320) void conv_pool_kernel(
    const float* __restrict__ x, const float* __restrict__ conv_w,
    const float* __restrict__ gamma, const float* __restrict__ beta,
    const float* __restrict__ mean, const float* __restrict__ var,
    const float* __restrict__ fc_w)
{
    __shared__ float img[IMGS * 784];
    int blk = blockIdx.x;
    int b0 = blk * IMGS;
    int t = threadIdx.x;

    int kc = t / 64, kin = t - kc * 64;

    if (blk < EMB) {   // fc_w row blk -> swizzled B split tiles (fc_w is [EMB][FEAT], K-major)
        float wv = fc_w[blk * FEAT + t];
        __nv_bfloat16 w1, w2; split2(wv, w1, w2);
        size_t off = ((size_t)((blk >> 7) * NCHUNK + kc)) * TILE_B + tile_off(blk & 127, kin);
        *(__nv_bfloat16*)(g_Bw[0] + off) = w1;
        *(__nv_bfloat16*)(g_Bw[1] + off) = w2;
    }

    const float* xb = x + (size_t)b0 * 784;
    for (int i = t; i < IMGS * 784; i += 320) img[i] = xb[i];

    int c = t >> 6, r = t & 63, py = r >> 3, px = r & 7;
    float w[9];
#pragma unroll
    for (int i = 0; i < 9; i++) w[i] = __ldg(&conv_w[c * 9 + i]);
    float s  = __ldg(&gamma[c]) / sqrtf(__ldg(&var[c]) + 1e-5f);
    float bb = __ldg(&beta[c]) - __ldg(&mean[c]) * s;
    __syncthreads();

    int y0 = py * 3, x0 = px * 3;
#pragma unroll
    for (int im = 0; im < IMGS; im++) {
        const float* ip = img + im * 784;
        float m = -3.402823466e38f;
#pragma unroll
        for (int dy = 0; dy < 3; dy++)
#pragma unroll
        for (int dx = 0; dx < 3; dx++) {
            float acc = 0.f;
#pragma unroll
            for (int i = 0; i < 3; i++)
#pragma unroll
            for (int j = 0; j < 3; j++)
                acc = fmaf(ip[(y0 + dy + i) * 28 + x0 + dx + j], w[i * 3 + j], acc);
            m = fmaxf(m, fmaf(acc, s, bb));
        }
        m = fmaxf(m, 0.f);
        int b = b0 + im;
        g_hf[(size_t)b * FEAT + t] = m;
        __nv_bfloat16 a1, a2; split2(m, a1, a2);
        size_t off = ((size_t)((b >> 7) * NCHUNK + kc)) * TILE_B + tile_off(b & 127, kin);
        *(__nv_bfloat16*)(g_Aw[0] + off) = a1;
        *(__nv_bfloat16*)(g_Aw[1] + off) = a2;
    }
}

// ============ kernel 2: PERSISTENT bulk-copy pipelined mma.sync 4-term split GEMM ============
// R11-proven mainloop; ring runs continuously across tiles (slot g%3, parity (g/3)&1);
// epilogue stores keys directly to g_z (STG.64, full sectors) — no smem reuse, no extra syncs
__global__ __launch_bounds__(256, 1) void gemm_kernel()
{
    extern __shared__ char smem[];
    const unsigned sbase = smem_u32(smem);
    const unsigned mb = sbase + 3 * STAGE_B;        // 3 mbarriers
    const int tid = threadIdx.x;
    const int wid = tid >> 5, l = tid & 31;
    const int wm = wid & 3;          // warp m-tile (32 rows)
    const int wn = wid >> 2;         // warp n-tile (64 cols)
    const int bid = blockIdx.x;

    const int ntile_mine = (NTILE - bid + GRID_P - 1) / GRID_P;

    if (tid == 0) {
        mbar_init(mb + 0, 1); mbar_init(mb + 8, 1); mbar_init(mb + 16, 1);
        asm volatile("fence.proxy.async.shared::cta;" ::: "memory");
    }
    __syncthreads();

    // stage g covers (tile index g/5, k-chunk g%5); ring slot g%3, parity (g/3)&1
    auto issue = [&](int g) {
        int i = g / 5;
        if (i >= ntile_mine) return;
        int tile = bid + i * GRID_P;
        int mt = tile >> 4, nt0 = tile & 15;
        int s = g - i * 5;
        unsigned slot = sbase + (g % 3) * STAGE_B;
        unsigned m = mb + (g % 3) * 8;
        mbar_expect_tx(m, STAGE_B);
        bulkcp(slot,             g_Aw[0] + ((size_t)(mt  * NCHUNK + s)) * TILE_B, TILE_B, m);
        bulkcp(slot + TILE_B,    g_Aw[1] + ((size_t)(mt  * NCHUNK + s)) * TILE_B, TILE_B, m);
        bulkcp(slot + 2*TILE_B,  g_Bw[0] + ((size_t)(nt0 * NCHUNK + s)) * TILE_B, TILE_B, m);
        bulkcp(slot + 3*TILE_B,  g_Bw[1] + ((size_t)(nt0 * NCHUNK + s)) * TILE_B, TILE_B, m);
    };
    if (tid == 0) { issue(0); issue(1); issue(2); }

    const unsigned s7 = l & 7;
    const unsigned aoff = (wm * 32 + (l & 15)) * 128;
    const unsigned boff = (wn * 64 + (l & 7)) * 128;
    const unsigned au = l >> 4;
    const unsigned bu = (l >> 3) & 1;

    for (int i = 0; i < ntile_mine; i++) {
        int tile = bid + i * GRID_P;
        int mt = tile >> 4, nt0 = tile & 15;

        float acc[2][8][4];
#pragma unroll
        for (int mh = 0; mh < 2; mh++)
#pragma unroll
            for (int nt = 0; nt < 8; nt++)
#pragma unroll
                for (int v = 0; v < 4; v++) acc[mh][nt][v] = 0.f;

        for (int s = 0; s < NCHUNK; s++) {
            int g = i * NCHUNK + s;
            mbar_wait(mb + (g % 3) * 8, (g / 3) & 1);
            unsigned base = sbase + (g % 3) * STAGE_B;
#pragma unroll
            for (int kk = 0; kk < 4; kk++) {
                unsigned ua = ((2 * kk + au) ^ s7) << 4;
                unsigned ub = ((2 * kk + bu) ^ s7) << 4;
                unsigned As[2][2][4], Bs[2][8][2];
#pragma unroll
                for (int sp = 0; sp < 2; sp++) {
                    unsigned Ab = base + sp * TILE_B + aoff + ua;
                    ldsm4(As[sp][0][0], As[sp][0][1], As[sp][0][2], As[sp][0][3], Ab);
                    ldsm4(As[sp][1][0], As[sp][1][1], As[sp][1][2], As[sp][1][3], Ab + 2048);
                    unsigned Bb = base + 2 * TILE_B + sp * TILE_B + boff + ub;
#pragma unroll
                    for (int nt = 0; nt < 8; nt++)
                        ldsm2(Bs[sp][nt][0], Bs[sp][nt][1], Bb + nt * 1024);
                }
                // products smallest-first: (A1,B1) (A1,B0) (A0,B1) (A0,B0)
#pragma unroll
                for (int p = 0; p < 4; p++) {
                    const int ia = (p < 2) ? 1 : 0;
                    const int ib = ((p & 1) == 0) ? 1 : 0;
#pragma unroll
                    for (int nt = 0; nt < 8; nt++) {
                        mma16816(acc[0][nt], As[ia][0], Bs[ib][nt]);
                        mma16816(acc[1][nt], As[ia][1], Bs[ib][nt]);
                    }
                }
            }
            __syncthreads();
            if (tid == 0) issue(g + 3);
        }

        // ---- epilogue: keys straight to g_z (each STG.64 lane-row segment = full 32B sector) ----
        unsigned* dst = g_z + (size_t)(mt * TM) * EMB + nt0 * TN;
#pragma unroll
        for (int mh = 0; mh < 2; mh++)
#pragma unroll
            for (int nt = 0; nt < 8; nt++) {
                int row = wm * 32 + mh * 16 + (l >> 2);
                int col = wn * 64 + nt * 8 + 2 * (l & 3);
                uint2 v01, v23;
                v01.x = f2key(acc[mh][nt][0]);
                v01.y = f2key(acc[mh][nt][1]);
                v23.x = f2key(acc[mh][nt][2]);
                v23.y = f2key(acc[mh][nt][3]);
                *(uint2*)(dst + (size_t)row * EMB + col)       = v01;
                *(uint2*)(dst + (size_t)(row + 8) * EMB + col) = v23;
            }
    }
}

// ============ kernel 3: per-row radix top-k + binarize + risky detection (proven) ============
__global__ __launch_bounds__(256) void select_kernel(float* __restrict__ out)
{
    __shared__ unsigned keys[EMB];
    __shared__ int hist[256];
    __shared__ int st[2];
    __shared__ unsigned red[16];
    int tid = threadIdx.x;
    int row = blockIdx.x;
    int wid = tid >> 5, l = tid & 31;

    const uint4* src = (const uint4*)(g_z + (size_t)row * EMB);
    ((uint4*)keys)[tid]       = src[tid];
    ((uint4*)keys)[tid + 256] = src[tid + 256];
    __syncthreads();

    int krem = KACT; unsigned prefix = 0, mask = 0;
    for (int pass = 0; pass < 4; pass++) {
        int shift = 24 - 8 * pass;
        hist[tid] = 0;
        __syncthreads();
        for (int i = tid; i < EMB; i += 256) {
            unsigned u = keys[i];
            if ((u & mask) == prefix) atomicAdd(&hist[(u >> shift) & 255], 1);
        }
        __syncthreads();
        radix_boundary(hist, krem, st, tid);
        __syncthreads();
        prefix |= ((unsigned)st[0]) << shift;
        krem = st[1];
        mask |= 0xFFu << shift;
    }

    // binarize + margin + tie count (single fused scan)
    unsigned thr = prefix;
    unsigned second = 0; int cnt = 0;
    float* o = out + (size_t)row * EMB;
#pragma unroll
    for (int i = 0; i < 8; i++) {
        unsigned u = keys[tid + i * 256];
        bool in = (u >= thr);
        o[tid + i * 256] = in ? 1.0f : 0.0f;
        if (in) cnt++;
        else if (u > second) second = u;
    }
#pragma unroll
    for (int off = 16; off; off >>= 1) {
        unsigned os = __shfl_xor_sync(0xffffffffu, second, off);
        if (os > second) second = os;
        cnt += __shfl_xor_sync(0xffffffffu, cnt, off);
    }
    if (l == 0) { red[wid] = second; red[8 + wid] = (unsigned)cnt; }
    __syncthreads();
    if (tid == 0) {
        unsigned s2 = 0; int ct = 0;
#pragma unroll
        for (int w = 0; w < 8; w++) { s2 = max(s2, red[w]); ct += (int)red[8 + w]; }
        float margin = key2f(thr) - key2f(s2);
        if (ct != KACT || !(margin > MARGIN_MIN)) {
            int p = atomicAdd(&g_nrisky, 1);
            g_risky[p] = row;
        }
    }
}

// ============ kernel 4: exact fixup, FAST (8 col-chains/thread, float4 w loads) ============
// per-column k-order is strictly sequential 0..319 -> bitwise-matches reference fp32 path
__global__ __launch_bounds__(256) void fixup_kernel(const float* __restrict__ fc_w,
                                                    float* __restrict__ out)
{
    __shared__ float hrow[FEAT];
    __shared__ unsigned keys[EMB];
    __shared__ int hist[256];
    __shared__ int st[2];
    int tid = threadIdx.x;
    int n = *(volatile int*)&g_nrisky;

    for (int it = blockIdx.x; it < n; it += gridDim.x) {
        int row = g_risky[it];
        for (int i = tid; i < FEAT; i += 256) hrow[i] = g_hf[(size_t)row * FEAT + i];
        __syncthreads();

        float acc[8];
#pragma unroll
        for (int c = 0; c < 8; c++) acc[c] = 0.f;
        const float4* w4 = (const float4*)fc_w;       // row pitch = 80 float4
#pragma unroll 4
        for (int k4 = 0; k4 < FEAT / 4; k4++) {
            float4 h4 = ((const float4*)hrow)[k4];
            float4 wv[8];
#pragma unroll
            for (int c = 0; c < 8; c++)
                wv[c] = w4[(size_t)(c * 256 + tid) * (FEAT / 4) + k4];
#pragma unroll
            for (int c = 0; c < 8; c++) {
                acc[c] = fmaf(h4.x, wv[c].x, acc[c]);
                acc[c] = fmaf(h4.y, wv[c].y, acc[c]);
                acc[c] = fmaf(h4.z, wv[c].z, acc[c]);
                acc[c] = fmaf(h4.w, wv[c].w, acc[c]);
            }
        }
#pragma unroll
        for (int c = 0; c < 8; c++) keys[c * 256 + tid] = f2key(acc[c]);
        __syncthreads();

        int krem = KACT; unsigned prefix = 0, mask = 0;
        for (int pass = 0; pass < 4; pass++) {
            int shift = 24 - 8 * pass;
            hist[tid] = 0;
            __syncthreads();
            for (int i = tid; i < EMB; i += 256) {
                unsigned u = keys[i];
                if ((u & mask) == prefix) atomicAdd(&hist[(u >> shift) & 255], 1);
            }
            __syncthreads();
            radix_boundary(hist, krem, st, tid);
            __syncthreads();
            prefix |= ((unsigned)st[0]) << shift;
            krem = st[1];
            mask |= 0xFFu << shift;
        }

        float* outp = out + (size_t)row * EMB;
        for (int i = tid; i < EMB; i += 256) outp[i] = (keys[i] >= prefix) ? 1.0f : 0.0f;
        __syncthreads();
    }
}

// ============ launch ============
extern "C" void kernel_launch(void* const* d_in, const int* in_sizes, int n_in,
                              void* d_out, int out_size)
{
    const float* x      = (const float*)d_in[0];
    const float* conv_w = (const float*)d_in[1];
    const float* gamma  = (const float*)d_in[2];
    const float* beta   = (const float*)d_in[3];
    const float* mean   = (const float*)d_in[4];
    const float* var    = (const float*)d_in[5];
    const float* fc_w   = (const float*)d_in[6];
    float* out = (float*)d_out;

    cudaFuncSetAttribute(gemm_kernel, cudaFuncAttributeMaxDynamicSharedMemorySize, SMEM_GEMM);

    reset_kernel<<<1, 1>>>();
    conv_pool_kernel<<<BATCH / IMGS, 320>>>(x, conv_w, gamma, beta, mean, var, fc_w);
    gemm_kernel<<<GRID_P, 256, SMEM_GEMM>>>();
    select_kernel<<<BATCH, 256>>>(out);
    fixup_kernel<<<1024, 256>>>(fc_w, out);
}

// round 15
// speedup vs baseline: 1.2546x; 1.0034x over previous
#include <cuda_runtime.h>
#include <cuda_bf16.h>

#define BATCH 32768
#define EMB   2048
#define FEAT  320
#define KACT  103          // ceil(0.05*2048)
#define MARGIN_MIN 4e-5f   // > 2*(|z_fast-z_exact| + |z_ref-z_exact|) bound (4-product split)
#define CANDN 64

// ---- GEMM tiling ----
#define TM 128
#define TN 128
#define NCHUNK 5           // FEAT / 64
#define NTILE  ((BATCH/TM)*(EMB/TN))   // 4096
#define GRID_P 148
#define TILE_B 16384       // one split tile: 128 rows x 128B (swizzled)
#define STAGE_B 65536      // A0,A1,B0,B1
#define SMEM_GEMM (3*STAGE_B + 64)   // 196672 (ring only; epilogue is direct-store)

// ---- device scratch (no allocs allowed) ----
// pre-swizzled tiled splits: [split][(tile*NCHUNK + chunk)*16KB]
__device__ __align__(16) char g_Aw[2][(BATCH/128) * NCHUNK * TILE_B];  // 2 x 20 MB
__device__ __align__(16) char g_Bw[2][(EMB/128)   * NCHUNK * TILE_B];  // 2 x 1.25 MB
__device__ float    g_hf[BATCH * FEAT];        // exact fp32 h for fixup, 42 MB
__device__ unsigned g_z[(size_t)BATCH * EMB];  // order-preserving z keys, 268 MB
__device__ int      g_nrisky;
__device__ int      g_risky[BATCH];

// ================= helpers =================
__device__ __forceinline__ unsigned smem_u32(const void* p) {
    unsigned a;
    asm("{ .reg .u64 t; cvta.to.shared.u64 t, %1; cvt.u32.u64 %0, t; }" : "=r"(a) : "l"(p));
    return a;
}
__device__ __forceinline__ void mbar_init(unsigned a, unsigned cnt) {
    asm volatile("mbarrier.init.shared.b64 [%0], %1;" :: "r"(a), "r"(cnt) : "memory");
}
__device__ __forceinline__ void mbar_expect_tx(unsigned a, unsigned bytes) {
    asm volatile("mbarrier.arrive.expect_tx.shared.b64 _, [%0], %1;" :: "r"(a), "r"(bytes) : "memory");
}
__device__ __forceinline__ void mbar_wait(unsigned a, unsigned parity) {
    asm volatile("{\n\t.reg .pred P;\n\tWL_%=:\n\t"
                 "mbarrier.try_wait.parity.acquire.cta.shared::cta.b64 P, [%0], %1, 0x989680;\n\t"
                 "@P bra.uni WD_%=;\n\tbra.uni WL_%=;\n\tWD_%=:\n\t}"
                 :: "r"(a), "r"(parity) : "memory");
}
__device__ __forceinline__ void bulkcp(unsigned dsmem, const void* gsrc, unsigned bytes, unsigned mbar) {
    asm volatile("cp.async.bulk.shared::cluster.global.mbarrier::complete_tx::bytes "
                 "[%0], [%1], %2, [%3];"
                 :: "r"(dsmem), "l"(gsrc), "r"(bytes), "r"(mbar) : "memory");
}
__device__ __forceinline__ void ldsm4(unsigned& r0, unsigned& r1, unsigned& r2, unsigned& r3, unsigned a) {
    asm volatile("ldmatrix.sync.aligned.m8n8.x4.shared.b16 {%0,%1,%2,%3}, [%4];"
                 : "=r"(r0), "=r"(r1), "=r"(r2), "=r"(r3) : "r"(a));
}
__device__ __forceinline__ void ldsm2(unsigned& r0, unsigned& r1, unsigned a) {
    asm volatile("ldmatrix.sync.aligned.m8n8.x2.shared.b16 {%0,%1}, [%2];"
                 : "=r"(r0), "=r"(r1) : "r"(a));
}
__device__ __forceinline__ void mma16816(float* c, const unsigned* a, const unsigned* b) {
    asm volatile("mma.sync.aligned.m16n8k16.row.col.f32.bf16.bf16.f32 "
                 "{%0,%1,%2,%3}, {%4,%5,%6,%7}, {%8,%9}, {%0,%1,%2,%3};"
                 : "+f"(c[0]), "+f"(c[1]), "+f"(c[2]), "+f"(c[3])
                 : "r"(a[0]), "r"(a[1]), "r"(a[2]), "r"(a[3]), "r"(b[0]), "r"(b[1]));
}
__device__ __forceinline__ void split2(float x, __nv_bfloat16& a, __nv_bfloat16& b) {
    a = __float2bfloat16_rn(x);
    b = __float2bfloat16_rn(x - __bfloat162float(a));
}
__device__ __forceinline__ unsigned f2key(float f) {
    unsigned u = __float_as_uint(f);
    return (u & 0x80000000u) ? ~u : (u | 0x80000000u);
}
__device__ __forceinline__ float key2f(unsigned u) {
    unsigned b = (u & 0x80000000u) ? (u & 0x7FFFFFFFu) : ~u;
    return __uint_as_float(b);
}
// byte offset of element (row rb in tile, k kin in chunk) inside a swizzled 16KB tile
__device__ __forceinline__ size_t tile_off(int rb, int kin) {
    return (size_t)(rb * 128 + ((((unsigned)kin >> 3) ^ (rb & 7)) << 4) + (kin & 7) * 2);
}

// boundary-bucket search: warp 0 computes (bucket, remaining k) from hist for krem
__device__ __forceinline__ void radix_boundary(int* hist, int krem, int* st, int tid) {
    if (tid < 32) {
        int ll = tid;
        int s = 0;
#pragma unroll
        for (int k = 0; k < 8; k++) s += hist[255 - (ll * 8 + k)];
        int cum = s;
#pragma unroll
        for (int off = 1; off < 32; off <<= 1) {
            int v = __shfl_up_sync(0xffffffffu, cum, off);
            if (ll >= off) cum += v;
        }
        unsigned ball = __ballot_sync(0xffffffffu, cum >= krem);
        int lstar = __ffs(ball) - 1;
        if (ll == lstar) {
            int cacc = cum - s;
            int bsel = 0, nk = krem;
#pragma unroll
            for (int k = 0; k < 8; k++) {
                int bkt = 255 - (ll * 8 + k);
                int h = hist[bkt];
                if (cacc + h >= krem) { bsel = bkt; nk = krem - cacc; break; }
                cacc += h;
            }
            st[0] = bsel; st[1] = nk;
        }
    }
}

__global__ void reset_kernel() { g_nrisky = 0; }

// ============ kernel 1: conv+bn+relu+maxpool, 4 images/block -> fp32 h + swizzled splits ============
#define IMGS 4
__global__ __launch_bounds__(320) void conv_pool_kernel(
    const float* __restrict__ x, const float* __restrict__ conv_w,
    const float* __restrict__ gamma, const float* __restrict__ beta,
    const float* __restrict__ mean, const float* __restrict__ var,
    const float* __restrict__ fc_w)
{
    __shared__ float img[IMGS * 784];
    int blk = blockIdx.x;
    int b0 = blk * IMGS;
    int t = threadIdx.x;

    int kc = t / 64, kin = t - kc * 64;

    if (blk < EMB) {   // fc_w row blk -> swizzled B split tiles (fc_w is [EMB][FEAT], K-major)
        float wv = fc_w[blk * FEAT + t];
        __nv_bfloat16 w1, w2; split2(wv, w1, w2);
        size_t off = ((size_t)((blk >> 7) * NCHUNK + kc)) * TILE_B + tile_off(blk & 127, kin);
        *(__nv_bfloat16*)(g_Bw[0] + off) = w1;
        *(__nv_bfloat16*)(g_Bw[1] + off) = w2;
    }

    const float* xb = x + (size_t)b0 * 784;
    for (int i = t; i < IMGS * 784; i += 320) img[i] = xb[i];

    int c = t >> 6, r = t & 63, py = r >> 3, px = r & 7;
    float w[9];
#pragma unroll
    for (int i = 0; i < 9; i++) w[i] = __ldg(&conv_w[c * 9 + i]);
    float s  = __ldg(&gamma[c]) / sqrtf(__ldg(&var[c]) + 1e-5f);
    float bb = __ldg(&beta[c]) - __ldg(&mean[c]) * s;
    __syncthreads();

    int y0 = py * 3, x0 = px * 3;
#pragma unroll
    for (int im = 0; im < IMGS; im++) {
        const float* ip = img + im * 784;
        float m = -3.402823466e38f;
#pragma unroll
        for (int dy = 0; dy < 3; dy++)
#pragma unroll
        for (int dx = 0; dx < 3; dx++) {
            float acc = 0.f;
#pragma unroll
            for (int i = 0; i < 3; i++)
#pragma unroll
            for (int j = 0; j < 3; j++)
                acc = fmaf(ip[(y0 + dy + i) * 28 + x0 + dx + j], w[i * 3 + j], acc);
            m = fmaxf(m, fmaf(acc, s, bb));
        }
        m = fmaxf(m, 0.f);
        int b = b0 + im;
        g_hf[(size_t)b * FEAT + t] = m;
        __nv_bfloat16 a1, a2; split2(m, a1, a2);
        size_t off = ((size_t)((b >> 7) * NCHUNK + kc)) * TILE_B + tile_off(b & 127, kin);
        *(__nv_bfloat16*)(g_Aw[0] + off) = a1;
        *(__nv_bfloat16*)(g_Aw[1] + off) = a2;
    }
}

// ============ kernel 2: PERSISTENT bulk-copy pipelined mma.sync 4-term split GEMM ============
// R14-proven: ring runs continuously across tiles; epilogue stores keys directly to g_z
__global__ __launch_bounds__(256, 1) void gemm_kernel()
{
    extern __shared__ char smem[];
    const unsigned sbase = smem_u32(smem);
    const unsigned mb = sbase + 3 * STAGE_B;        // 3 mbarriers
    const int tid = threadIdx.x;
    const int wid = tid >> 5, l = tid & 31;
    const int wm = wid & 3;          // warp m-tile (32 rows)
    const int wn = wid >> 2;         // warp n-tile (64 cols)
    const int bid = blockIdx.x;

    const int ntile_mine = (NTILE - bid + GRID_P - 1) / GRID_P;

    if (tid == 0) {
        mbar_init(mb + 0, 1); mbar_init(mb + 8, 1); mbar_init(mb + 16, 1);
        asm volatile("fence.proxy.async.shared::cta;" ::: "memory");
    }
    __syncthreads();

    // stage g covers (tile index g/5, k-chunk g%5); ring slot g%3, parity (g/3)&1
    auto issue = [&](int g) {
        int i = g / 5;
        if (i >= ntile_mine) return;
        int tile = bid + i * GRID_P;
        int mt = tile >> 4, nt0 = tile & 15;
        int s = g - i * 5;
        unsigned slot = sbase + (g % 3) * STAGE_B;
        unsigned m = mb + (g % 3) * 8;
        mbar_expect_tx(m, STAGE_B);
        bulkcp(slot,             g_Aw[0] + ((size_t)(mt  * NCHUNK + s)) * TILE_B, TILE_B, m);
        bulkcp(slot + TILE_B,    g_Aw[1] + ((size_t)(mt  * NCHUNK + s)) * TILE_B, TILE_B, m);
        bulkcp(slot + 2*TILE_B,  g_Bw[0] + ((size_t)(nt0 * NCHUNK + s)) * TILE_B, TILE_B, m);
        bulkcp(slot + 3*TILE_B,  g_Bw[1] + ((size_t)(nt0 * NCHUNK + s)) * TILE_B, TILE_B, m);
    };
    if (tid == 0) { issue(0); issue(1); issue(2); }

    const unsigned s7 = l & 7;
    const unsigned aoff = (wm * 32 + (l & 15)) * 128;
    const unsigned boff = (wn * 64 + (l & 7)) * 128;
    const unsigned au = l >> 4;
    const unsigned bu = (l >> 3) & 1;

    for (int i = 0; i < ntile_mine; i++) {
        int tile = bid + i * GRID_P;
        int mt = tile >> 4, nt0 = tile & 15;

        float acc[2][8][4];
#pragma unroll
        for (int mh = 0; mh < 2; mh++)
#pragma unroll
            for (int nt = 0; nt < 8; nt++)
#pragma unroll
                for (int v = 0; v < 4; v++) acc[mh][nt][v] = 0.f;

        for (int s = 0; s < NCHUNK; s++) {
            int g = i * NCHUNK + s;
            mbar_wait(mb + (g % 3) * 8, (g / 3) & 1);
            unsigned base = sbase + (g % 3) * STAGE_B;
#pragma unroll
            for (int kk = 0; kk < 4; kk++) {
                unsigned ua = ((2 * kk + au) ^ s7) << 4;
                unsigned ub = ((2 * kk + bu) ^ s7) << 4;
                unsigned As[2][2][4], Bs[2][8][2];
#pragma unroll
                for (int sp = 0; sp < 2; sp++) {
                    unsigned Ab = base + sp * TILE_B + aoff + ua;
                    ldsm4(As[sp][0][0], As[sp][0][1], As[sp][0][2], As[sp][0][3], Ab);
                    ldsm4(As[sp][1][0], As[sp][1][1], As[sp][1][2], As[sp][1][3], Ab + 2048);
                    unsigned Bb = base + 2 * TILE_B + sp * TILE_B + boff + ub;
#pragma unroll
                    for (int nt = 0; nt < 8; nt++)
                        ldsm2(Bs[sp][nt][0], Bs[sp][nt][1], Bb + nt * 1024);
                }
                // products smallest-first: (A1,B1) (A1,B0) (A0,B1) (A0,B0)
#pragma unroll
                for (int p = 0; p < 4; p++) {
                    const int ia = (p < 2) ? 1 : 0;
                    const int ib = ((p & 1) == 0) ? 1 : 0;
#pragma unroll
                    for (int nt = 0; nt < 8; nt++) {
                        mma16816(acc[0][nt], As[ia][0], Bs[ib][nt]);
                        mma16816(acc[1][nt], As[ia][1], Bs[ib][nt]);
                    }
                }
            }
            __syncthreads();
            if (tid == 0) issue(g + 3);
        }

        // ---- epilogue: keys straight to g_z (each STG.64 lane-row segment = full 32B sector) ----
        unsigned* dst = g_z + (size_t)(mt * TM) * EMB + nt0 * TN;
#pragma unroll
        for (int mh = 0; mh < 2; mh++)
#pragma unroll
            for (int nt = 0; nt < 8; nt++) {
                int row = wm * 32 + mh * 16 + (l >> 2);
                int col = wn * 64 + nt * 8 + 2 * (l & 3);
                uint2 v01, v23;
                v01.x = f2key(acc[mh][nt][0]);
                v01.y = f2key(acc[mh][nt][1]);
                v23.x = f2key(acc[mh][nt][2]);
                v23.y = f2key(acc[mh][nt][3]);
                *(uint2*)(dst + (size_t)row * EMB + col)       = v01;
                *(uint2*)(dst + (size_t)(row + 8) * EMB + col) = v23;
            }
    }
}

// ============ kernel 3: per-row top-k — 2 full radix passes + candidate narrowing ============
__global__ __launch_bounds__(256) void select_kernel(float* __restrict__ out)
{
    __shared__ unsigned keys[EMB];
    __shared__ unsigned cand[CANDN];
    __shared__ int hist[256];
    __shared__ int st[3];                 // {bucket, krem, gather count}
    __shared__ unsigned red[16];
    int tid = threadIdx.x;
    int row = blockIdx.x;
    int wid = tid >> 5, l = tid & 31;

    const uint4* src = (const uint4*)(g_z + (size_t)row * EMB);
    ((uint4*)keys)[tid]       = src[tid];
    ((uint4*)keys)[tid + 256] = src[tid + 256];
    if (tid == 0) st[2] = 0;
    __syncthreads();

    // ---- pass 0 (bits 31-24) ----
    hist[tid] = 0;
    __syncthreads();
#pragma unroll
    for (int i = 0; i < 8; i++) atomicAdd(&hist[keys[tid + i * 256] >> 24], 1);
    __syncthreads();
    radix_boundary(hist, KACT, st, tid);
    __syncthreads();
    unsigned prefix = ((unsigned)st[0]) << 24;
    int krem = st[1];
    __syncthreads();

    // ---- pass 1 (bits 23-16) ----
    hist[tid] = 0;
    __syncthreads();
#pragma unroll
    for (int i = 0; i < 8; i++) {
        unsigned u = keys[tid + i * 256];
        if ((u & 0xFF000000u) == prefix) atomicAdd(&hist[(u >> 16) & 255], 1);
    }
    __syncthreads();
    radix_boundary(hist, krem, st, tid);
    __syncthreads();
    int c1 = hist[st[0]];                 // # keys sharing the 16-bit boundary prefix
    prefix |= ((unsigned)st[0]) << 16;
    krem = st[1];
    __syncthreads();

    unsigned thr;
    if (c1 <= CANDN) {
        // gather the c1 candidates (tiny; atomic pressure negligible)
#pragma unroll
        for (int i = 0; i < 8; i++) {
            unsigned u = keys[tid + i * 256];
            if ((u & 0xFFFF0000u) == prefix) cand[atomicAdd(&st[2], 1)] = u;
        }
        __syncthreads();
        int nc = st[2];
        // passes 2,3 over candidates only
        unsigned mask = 0xFFFF0000u;
        for (int pass = 2; pass < 4; pass++) {
            int shift = 24 - 8 * pass;
            hist[tid] = 0;
            __syncthreads();
            for (int i = tid; i < nc; i += 256) {
                unsigned u = cand[i];
                if ((u & mask) == prefix) atomicAdd(&hist[(u >> shift) & 255], 1);
            }
            __syncthreads();
            radix_boundary(hist, krem, st, tid);
            __syncthreads();
            prefix |= ((unsigned)st[0]) << shift;
            krem = st[1];
            mask |= 0xFFu << shift;
            __syncthreads();
        }
        thr = prefix;
    } else {
        // rare fallback: full passes 2,3
        unsigned mask = 0xFFFF0000u;
        for (int pass = 2; pass < 4; pass++) {
            int shift = 24 - 8 * pass;
            hist[tid] = 0;
            __syncthreads();
            for (int i = tid; i < EMB; i += 256) {
                unsigned u = keys[i];
                if ((u & mask) == prefix) atomicAdd(&hist[(u >> shift) & 255], 1);
            }
            __syncthreads();
            radix_boundary(hist, krem, st, tid);
            __syncthreads();
            prefix |= ((unsigned)st[0]) << shift;
            krem = st[1];
            mask |= 0xFFu << shift;
            __syncthreads();
        }
        thr = prefix;
    }

    // binarize + margin + tie count (single fused scan)
    unsigned second = 0; int cnt = 0;
    float* o = out + (size_t)row * EMB;
#pragma unroll
    for (int i = 0; i < 8; i++) {
        unsigned u = keys[tid + i * 256];
        bool in = (u >= thr);
        o[tid + i * 256] = in ? 1.0f : 0.0f;
        if (in) cnt++;
        else if (u > second) second = u;
    }
#pragma unroll
    for (int off = 16; off; off >>= 1) {
        unsigned os = __shfl_xor_sync(0xffffffffu, second, off);
        if (os > second) second = os;
        cnt += __shfl_xor_sync(0xffffffffu, cnt, off);
    }
    if (l == 0) { red[wid] = second; red[8 + wid] = (unsigned)cnt; }
    __syncthreads();
    if (tid == 0) {
        unsigned s2 = 0; int ct = 0;
#pragma unroll
        for (int w = 0; w < 8; w++) { s2 = max(s2, red[w]); ct += (int)red[8 + w]; }
        float margin = key2f(thr) - key2f(s2);
        if (ct != KACT || !(margin > MARGIN_MIN)) {
            int p = atomicAdd(&g_nrisky, 1);
            g_risky[p] = row;
        }
    }
}

// ============ kernel 4: exact fixup, FAST (8 col-chains/thread, float4 w loads) ============
// per-column k-order is strictly sequential 0..319 -> bitwise-matches reference fp32 path
__global__ __launch_bounds__(256) void fixup_kernel(const float* __restrict__ fc_w,
                                                    float* __restrict__ out)
{
    __shared__ float hrow[FEAT];
    __shared__ unsigned keys[EMB];
    __shared__ int hist[256];
    __shared__ int st[2];
    int tid = threadIdx.x;
    int n = *(volatile int*)&g_nrisky;

    for (int it = blockIdx.x; it < n; it += gridDim.x) {
        int row = g_risky[it];
        for (int i = tid; i < FEAT; i += 256) hrow[i] = g_hf[(size_t)row * FEAT + i];
        __syncthreads();

        float acc[8];
#pragma unroll
        for (int c = 0; c < 8; c++) acc[c] = 0.f;
        const float4* w4 = (const float4*)fc_w;       // row pitch = 80 float4
#pragma unroll 4
        for (int k4 = 0; k4 < FEAT / 4; k4++) {
            float4 h4 = ((const float4*)hrow)[k4];
            float4 wv[8];
#pragma unroll
            for (int c = 0; c < 8; c++)
                wv[c] = w4[(size_t)(c * 256 + tid) * (FEAT / 4) + k4];
#pragma unroll
            for (int c = 0; c < 8; c++) {
                acc[c] = fmaf(h4.x, wv[c].x, acc[c]);
                acc[c] = fmaf(h4.y, wv[c].y, acc[c]);
                acc[c] = fmaf(h4.z, wv[c].z, acc[c]);
                acc[c] = fmaf(h4.w, wv[c].w, acc[c]);
            }
        }
#pragma unroll
        for (int c = 0; c < 8; c++) keys[c * 256 + tid] = f2key(acc[c]);
        __syncthreads();

        int krem = KACT; unsigned prefix = 0, mask = 0;
        for (int pass = 0; pass < 4; pass++) {
            int shift = 24 - 8 * pass;
            hist[tid] = 0;
            __syncthreads();
            for (int i = tid; i < EMB; i += 256) {
                unsigned u = keys[i];
                if ((u & mask) == prefix) atomicAdd(&hist[(u >> shift) & 255], 1);
            }
            __syncthreads();
            radix_boundary(hist, krem, st, tid);
            __syncthreads();
            prefix |= ((unsigned)st[0]) << shift;
            krem = st[1];
            mask |= 0xFFu << shift;
        }

        float* outp = out + (size_t)row * EMB;
        for (int i = tid; i < EMB; i += 256) outp[i] = (keys[i] >= prefix) ? 1.0f : 0.0f;
        __syncthreads();
    }
}

// ============ launch ============
extern "C" void kernel_launch(void* const* d_in, const int* in_sizes, int n_in,
                              void* d_out, int out_size)
{
    const float* x      = (const float*)d_in[0];
    const float* conv_w = (const float*)d_in[1];
    const float* gamma  = (const float*)d_in[2];
    const float* beta   = (const float*)d_in[3];
    const float* mean   = (const float*)d_in[4];
    const float* var    = (const float*)d_in[5];
    const float* fc_w   = (const float*)d_in[6];
    float* out = (float*)d_out;

    cudaFuncSetAttribute(gemm_kernel, cudaFuncAttributeMaxDynamicSharedMemorySize, SMEM_GEMM);

    reset_kernel<<<1, 1>>>();
    conv_pool_kernel<<<BATCH / IMGS, 320>>>(x, conv_w, gamma, beta, mean, var, fc_w);
    gemm_kernel<<<GRID_P, 256, SMEM_GEMM>>>();
    select_kernel<<<BATCH, 256>>>(out);
    fixup_kernel<<<1024, 256>>>(fc_w, out);
}